// round 17
// baseline (speedup 1.0000x reference)
#include <cuda_runtime.h>
#include <cuda_bf16.h>
#include <cuda_fp16.h>
#include <cstdint>

#define NTOK 4096
#define CDIM 256
#define FDIM 64
#define BATCH 8
#define SHIFT 30.0f

// Scratch (allocation-free rule: __device__ globals)
__device__ __half g_wT[384 * CDIM];                   // [Wf|Wg|Wh]^T fp16, permq k
__device__ __half g_wvT[CDIM * CDIM];                 // Wv^T fp16, permq k
__device__ __half g_f[BATCH * NTOK * FDIM];           // [tok][feat] natural fp16
__device__ __half g_g[BATCH * NTOK * FDIM];           // [tok][feat quad-perm] fp16
__device__ __nv_bfloat16 g_hT[BATCH * CDIM * NTOK];   // [ch][tok-permuted] bf16
__device__ __half g_o16[BATCH * NTOK * CDIM];         // attention out fp16, permq ch

// ---------------------------------------------------------------------------
// helpers
// ---------------------------------------------------------------------------
__device__ __forceinline__ void mma_f16(float c[4], const unsigned a[4],
                                        unsigned b0, unsigned b1) {
    asm volatile(
        "mma.sync.aligned.m16n8k16.row.col.f32.f16.f16.f32 "
        "{%0,%1,%2,%3}, {%4,%5,%6,%7}, {%8,%9}, {%0,%1,%2,%3};"
        : "+f"(c[0]), "+f"(c[1]), "+f"(c[2]), "+f"(c[3])
        : "r"(a[0]), "r"(a[1]), "r"(a[2]), "r"(a[3]), "r"(b0), "r"(b1));
}

__device__ __forceinline__ void mma_bf16(float c[4], const unsigned a[4],
                                         unsigned b0, unsigned b1) {
    asm volatile(
        "mma.sync.aligned.m16n8k16.row.col.f32.bf16.bf16.f32 "
        "{%0,%1,%2,%3}, {%4,%5,%6,%7}, {%8,%9}, {%0,%1,%2,%3};"
        : "+f"(c[0]), "+f"(c[1]), "+f"(c[2]), "+f"(c[3])
        : "r"(a[0]), "r"(a[1]), "r"(a[2]), "r"(a[3]), "r"(b0), "r"(b1));
}

__device__ __forceinline__ unsigned pk_bf16x2(float lo, float hi) {
    unsigned r;
    asm("cvt.rn.bf16x2.f32 %0, %1, %2;" : "=r"(r) : "f"(hi), "f"(lo));
    return r;
}

__device__ __forceinline__ unsigned pk_f16x2(float lo, float hi) {
    unsigned r;
    asm("cvt.rn.f16x2.f32 %0, %1, %2;" : "=r"(r) : "f"(hi), "f"(lo));
    return r;
}

__device__ __forceinline__ void cp_async16(void* sdst, const void* gsrc) {
    unsigned int saddr = (unsigned int)__cvta_generic_to_shared(sdst);
    asm volatile("cp.async.cg.shared.global [%0], [%1], 16;"
                 :: "r"(saddr), "l"(gsrc));
}
#define CP_COMMIT() asm volatile("cp.async.commit_group;")
#define CP_WAIT0()  asm volatile("cp.async.wait_group 0;")

// feature quad-permute: halves (2t,2t+1,2t+8,2t+9) contiguous per 16-block
__device__ __forceinline__ int permq(int n) {
    return (n & ~15) | (((n >> 1) & 3) << 2) | (((n >> 3) & 1) << 1) | (n & 1);
}
__device__ __forceinline__ int ptok_of(int tok) {
    int t16 = tok & 15;
    int w = t16 >> 1, ln = t16 & 1;
    int p = ((w & 3) << 1) | (w >> 2);
    return (tok & ~15) | (p << 1) | ln;
}

// ---------------------------------------------------------------------------
// cvt_w: weights fp32 -> fp16 transposed K-major (tiny, one-off)
// ---------------------------------------------------------------------------
__global__ __launch_bounds__(256) void cvt_w_k(
    const float* __restrict__ Wf, const float* __restrict__ Wg,
    const float* __restrict__ Wh, const float* __restrict__ Wv) {
    int i = blockIdx.x * 256 + threadIdx.x;
    if (i < 384 * 256) {
        int n = i >> 8, k = i & 255;
        float v = (n < 64) ? Wf[k * 64 + n]
                : (n < 128) ? Wg[k * 64 + (n - 64)]
                            : Wh[k * 256 + (n - 128)];
        g_wT[n * CDIM + permq(k)] = __float2half(v);
    } else {
        int j = i - 384 * 256;
        int n = j >> 8, k = j & 255;
        g_wvT[n * CDIM + permq(k)] = __float2half(Wv[k * CDIM + n]);
    }
}

// ---------------------------------------------------------------------------
// proj_k: fused f/g/hT projection, fp16 m16n8k16.
// NEW vs R16: K32 steps (8 iterations, 1 barrier each), 2-stage buffer.
// xs stride 44 floats (12g mod 32 distinct); ws stride 40 halves (80B rows,
// 16B-aligned chunks, 10g mod 16 distinct).
// ---------------------------------------------------------------------------
struct ProjSmem {
    float  xs[2][64][44];    // 22528 B
    __half ws[2][384][40];   // 61440 B
};                            // 83968 B; hstage (36864 B) aliases post-loop
#define HSTAGE_STRIDE 72
#define PROJ_SMEM ((int)sizeof(ProjSmem))

__global__ __launch_bounds__(512) void proj_k(const float* __restrict__ x) {
    extern __shared__ char sraw[];
    ProjSmem& sm = *reinterpret_cast<ProjSmem*>(sraw);
    __nv_bfloat16* hstage = reinterpret_cast<__nv_bfloat16*>(sraw);

    const int tid  = threadIdx.x;
    const int wid  = tid >> 5;
    const int lane = tid & 31;
    const int g    = lane >> 2;
    const int tg   = lane & 3;
    const int rg   = wid & 3;
    const int cgp  = wid >> 2;
    const int m0   = blockIdx.x * 64;

    // k32 prefetch: xs 512 chunks (1/thread), ws 1536 chunks (3/thread)
#define PROJ_PREF(KS, BUF)                                                  \
    do {                                                                    \
        {                                                                   \
            int r = tid >> 3, c = tid & 7;                                  \
            cp_async16(&sm.xs[BUF][r][c << 2],                              \
                       x + (size_t)(m0 + r) * CDIM + (KS) * 32 + (c << 2)); \
        }                                                                   \
        _Pragma("unroll")                                                   \
        for (int q = 0; q < 3; q++) {                                       \
            int cid = q * 512 + tid;                                        \
            int rr = cid >> 2, cc = cid & 3;                                \
            cp_async16(&sm.ws[BUF][rr][cc << 3],                            \
                       g_wT + (size_t)rr * CDIM + (KS) * 32 + (cc << 3));   \
        }                                                                   \
        CP_COMMIT();                                                        \
    } while (0)

    float acc[12][4];
#pragma unroll
    for (int nb = 0; nb < 12; nb++)
#pragma unroll
        for (int q = 0; q < 4; q++) acc[nb][q] = 0.0f;

    PROJ_PREF(0, 0);

    for (int ks = 0; ks < 8; ks++) {
        const int buf = ks & 1;
        CP_WAIT0();
        __syncthreads();
        if (ks + 1 < 8) PROJ_PREF(ks + 1, buf ^ 1);

#pragma unroll
        for (int kb = 0; kb < 2; kb++) {
            unsigned a[4];
            {
                const int r0 = (rg << 4) + g;
                const int kc = kb * 16 + 2 * tg;
                float2 u0 = *(const float2*)&sm.xs[buf][r0][kc];
                float2 u1 = *(const float2*)&sm.xs[buf][r0 + 8][kc];
                float2 v0 = *(const float2*)&sm.xs[buf][r0][kc + 8];
                float2 v1 = *(const float2*)&sm.xs[buf][r0 + 8][kc + 8];
                a[0] = pk_f16x2(u0.x, u0.y);
                a[1] = pk_f16x2(u1.x, u1.y);
                a[2] = pk_f16x2(v0.x, v0.y);
                a[3] = pk_f16x2(v1.x, v1.y);
            }
#pragma unroll
            for (int nb = 0; nb < 12; nb++) {
                int rown = cgp * 96 + nb * 8 + g;
                uint2 bb = *(const uint2*)&sm.ws[buf][rown][kb * 16 + (tg << 2)];
                mma_f16(acc[nb], a, bb.x, bb.y);
            }
        }
    }

    const int row0 = m0 + (rg << 4) + g;
    const int row1 = row0 + 8;
    const int lt0  = (rg << 4) + g;
    const int lt1  = lt0 + 8;
    const int pt_l0 = ptok_of(lt0) & 63;
    const int pt_l1 = ptok_of(lt1) & 63;

    // f and g: direct stores
#pragma unroll
    for (int nb = 0; nb < 12; nb++) {
        int nbg = cgp * 12 + nb;
        if (nbg < 8) {
            int col = nbg * 8 + (tg << 1);
            *(__half2*)&g_f[(size_t)row0 * FDIM + col] =
                __floats2half2_rn(acc[nb][0], acc[nb][1]);
            *(__half2*)&g_f[(size_t)row1 * FDIM + col] =
                __floats2half2_rn(acc[nb][2], acc[nb][3]);
        } else if (nbg < 16) {
            int nl = (nbg - 8) * 8 + (tg << 1);
            int pos = permq(nl);
            *(__half2*)&g_g[(size_t)row0 * FDIM + pos] =
                __floats2half2_rn(acc[nb][0], acc[nb][1]);
            *(__half2*)&g_g[(size_t)row1 * FDIM + pos] =
                __floats2half2_rn(acc[nb][2], acc[nb][3]);
        }
    }

    // h: stage into smem [256 ch][72] bf16 at permuted token positions
    __syncthreads();  // xs/ws dead; hstage aliasing safe
#pragma unroll
    for (int nb = 0; nb < 12; nb++) {
        int nbg = cgp * 12 + nb;
        if (nbg >= 16) {
            int ch0 = (nbg - 16) * 8 + (tg << 1);
            hstage[ch0 * HSTAGE_STRIDE + pt_l0]       = __float2bfloat16(acc[nb][0]);
            hstage[(ch0 + 1) * HSTAGE_STRIDE + pt_l0] = __float2bfloat16(acc[nb][1]);
            hstage[ch0 * HSTAGE_STRIDE + pt_l1]       = __float2bfloat16(acc[nb][2]);
            hstage[(ch0 + 1) * HSTAGE_STRIDE + pt_l1] = __float2bfloat16(acc[nb][3]);
        }
    }
    __syncthreads();

    // cooperative coalesced hT store: 256 ch x 64 tok = 2048 16B-chunks
    {
        const int bb = row0 >> 12;
        const int tok0 = m0 & (NTOK - 1);
#pragma unroll
        for (int c = tid; c < 2048; c += 512) {
            int ch = c >> 3, part = c & 7;
            uint4 v = *(const uint4*)&hstage[ch * HSTAGE_STRIDE + part * 8];
            *(uint4*)&g_hT[((size_t)bb * CDIM + ch) * NTOK + tok0 + part * 8] = v;
        }
    }
#undef PROJ_PREF
}

// ---------------------------------------------------------------------------
// epi_k: out = gamma*(o @ Wv) + x, fp16 m16n8k16.
// NEW vs R16: K32 steps (8 iterations, 1 barrier each), 2-stage buffer.
// os/ws stride 40 halves (80B rows, 16B-aligned, conflict-free).
// ---------------------------------------------------------------------------
struct EpiSmem {
    __half os[2][64][40];    // 10240 B
    __half ws[2][256][40];   // 40960 B
};                            // 51200 B

__global__ __launch_bounds__(512) void epi_k(
    const float* __restrict__ X, const float* __restrict__ gamma,
    float* __restrict__ out)
{
    extern __shared__ char sraw[];
    EpiSmem& sm = *reinterpret_cast<EpiSmem*>(sraw);

    const int tid  = threadIdx.x;
    const int wid  = tid >> 5;
    const int lane = tid & 31;
    const int g    = lane >> 2;
    const int tg   = lane & 3;
    const int rg   = wid & 3;
    const int cgp  = wid >> 2;
    const int m0   = blockIdx.x * 64;

    // k32 prefetch: os 256 chunks, ws 1024 chunks (2/thread)
#define EPI_PREF(KS, BUF)                                                   \
    do {                                                                    \
        if (tid < 256) {                                                    \
            int r = tid >> 2, c = tid & 3;                                  \
            cp_async16(&sm.os[BUF][r][c << 3],                              \
                       g_o16 + (size_t)(m0 + r) * CDIM + (KS) * 32 + (c << 3)); \
        }                                                                   \
        _Pragma("unroll")                                                   \
        for (int q = 0; q < 2; q++) {                                       \
            int cid = q * 512 + tid;                                        \
            int rr = cid >> 2, cc = cid & 3;                                \
            cp_async16(&sm.ws[BUF][rr][cc << 3],                            \
                       g_wvT + (size_t)rr * CDIM + (KS) * 32 + (cc << 3));  \
        }                                                                   \
        CP_COMMIT();                                                        \
    } while (0)

    float acc[8][4];
#pragma unroll
    for (int nb = 0; nb < 8; nb++)
#pragma unroll
        for (int q = 0; q < 4; q++) acc[nb][q] = 0.0f;

    EPI_PREF(0, 0);

    for (int ks = 0; ks < 8; ks++) {
        const int buf = ks & 1;
        CP_WAIT0();
        __syncthreads();
        if (ks + 1 < 8) EPI_PREF(ks + 1, buf ^ 1);

#pragma unroll
        for (int kb = 0; kb < 2; kb++) {
            unsigned a[4];
            {
                const int r0 = (rg << 4) + g;
                const int kc = kb * 16 + (tg << 2);
                uint2 t0 = *(const uint2*)&sm.os[buf][r0][kc];
                uint2 t1 = *(const uint2*)&sm.os[buf][r0 + 8][kc];
                a[0] = t0.x; a[2] = t0.y; a[1] = t1.x; a[3] = t1.y;
            }
#pragma unroll
            for (int nb = 0; nb < 8; nb++) {
                int rown = cgp * 64 + nb * 8 + g;
                uint2 bb = *(const uint2*)&sm.ws[buf][rown][kb * 16 + (tg << 2)];
                mma_f16(acc[nb], a, bb.x, bb.y);
            }
        }
    }

    const float gam = *gamma;
    const int row0 = m0 + (rg << 4) + g;
    const int row1 = row0 + 8;
#pragma unroll
    for (int nb = 0; nb < 8; nb++) {
        int col = cgp * 64 + nb * 8 + (tg << 1);
        float2 x0 = *(const float2*)&X[(size_t)row0 * CDIM + col];
        float2 x1 = *(const float2*)&X[(size_t)row1 * CDIM + col];
        *(float2*)&out[(size_t)row0 * CDIM + col] =
            make_float2(gam * acc[nb][0] + x0.x, gam * acc[nb][1] + x0.y);
        *(float2*)&out[(size_t)row1 * CDIM + col] =
            make_float2(gam * acc[nb][2] + x1.x, gam * acc[nb][3] + x1.y);
    }
#undef EPI_PREF
}

// ---------------------------------------------------------------------------
// Flash attention (byte-identical to R14-R16 passing): fp16 S + bf16 PV,
// fixed-shift softmax, S de-dup via smem P exchange, 128-row i-tile.
// ---------------------------------------------------------------------------
struct AttnSmem {
    unsigned gs[2][64][32];    // g j-tile fp16x2   16384 B
    unsigned hT[2][256][32];   // hT j-tile bf16x2  65536 B
    unsigned P[128][32];       // P tile bf16x2     16384 B
    float redL[2][128];        // cw-partial row sums 1024 B
};                              // 99328 B

__global__ __launch_bounds__(256, 1) void attn_k() {
    extern __shared__ char sraw[];
    AttnSmem& sm = *reinterpret_cast<AttnSmem*>(sraw);

    const int tid  = threadIdx.x;
    const int wid  = tid >> 5;
    const int lane = tid & 31;
    const int g    = lane >> 2;     // 0..7
    const int tg   = lane & 3;      // 0..3
    const int rw   = wid & 3;       // row group (32 rows)
    const int cw   = wid >> 2;      // 0..1: S j-col half + PV channel half
    const int g4   = (g & 3) << 2;  // chunk swizzle bits

    const int b  = blockIdx.y;
    const int i0 = blockIdx.x * 128;

    const __half* __restrict__ fb = g_f + (size_t)b * NTOK * FDIM;
    const __half* __restrict__ gbase = g_g + (size_t)b * NTOK * FDIM;
    const __nv_bfloat16* __restrict__ hTb = g_hT + (size_t)b * CDIM * NTOK;

#define PREFETCH_TILE(J0, BUF)                                              \
    do {                                                                    \
        {                                                                   \
            int r = tid >> 2;                                               \
            const __half* gsrc = gbase + (size_t)((J0) + r) * FDIM;         \
            int sw = (r & 3) << 1;                                          \
            _Pragma("unroll")                                               \
            for (int q = 0; q < 2; q++) {                                   \
                int cl = (tid & 3) + q * 4;                                 \
                cp_async16(&sm.gs[BUF][r][(cl ^ sw) << 2], gsrc + (cl << 3)); \
            }                                                               \
        }                                                                   \
        {                                                                   \
            int r0 = tid >> 1;                                              \
            _Pragma("unroll")                                               \
            for (int h = 0; h < 2; h++) {                                   \
                int r = r0 + h * 128;                                       \
                const __nv_bfloat16* hsrc = hTb + (size_t)r * NTOK + (J0);  \
                int sw = (r & 3) << 1;                                      \
                _Pragma("unroll")                                           \
                for (int qq = 0; qq < 4; qq++) {                            \
                    int cl = ((tid & 1) << 2) + qq;                         \
                    cp_async16(&sm.hT[BUF][r][(cl ^ sw) << 2],              \
                               hsrc + (cl << 3));                           \
                }                                                           \
            }                                                               \
        }                                                                   \
        CP_COMMIT();                                                        \
    } while (0)

    // persistent f A-fragments (fp16): 2 m16 blocks x 4 k16 chunks
    unsigned aF[2][4][4];
#pragma unroll
    for (int mi = 0; mi < 2; mi++) {
        int row0 = i0 + (rw << 5) + (mi << 4) + g;
#pragma unroll
        for (int kb = 0; kb < 4; kb++) {
            int k0 = kb * 16 + 2 * tg;
            aF[mi][kb][0] = *(const unsigned*)(fb + (size_t)row0 * FDIM + k0);
            aF[mi][kb][1] = *(const unsigned*)(fb + (size_t)(row0 + 8) * FDIM + k0);
            aF[mi][kb][2] = *(const unsigned*)(fb + (size_t)row0 * FDIM + k0 + 8);
            aF[mi][kb][3] = *(const unsigned*)(fb + (size_t)(row0 + 8) * FDIM + k0 + 8);
        }
    }

    float acc[2][16][4];
#pragma unroll
    for (int mi = 0; mi < 2; mi++)
#pragma unroll
        for (int nb = 0; nb < 16; nb++)
#pragma unroll
            for (int q = 0; q < 4; q++) acc[mi][nb][q] = 0.0f;

    float L[2][2] = {{0.f, 0.f}, {0.f, 0.f}};  // partial (this cw's 32 cols)

    PREFETCH_TILE(0, 0);

    for (int t = 0; t < NTOK / 64; t++) {
        const int buf = t & 1;

        CP_WAIT0();
        __syncthreads();  // buf ready; prev tile's PV done with P

        if (t + 1 < NTOK / 64) {
            PREFETCH_TILE((t + 1) * 64, buf ^ 1);
        }

        // ---- S phase: this warp's 2 k4 groups (32 j-cols) ----
#pragma unroll
        for (int kq = 0; kq < 2; kq++) {
            int k4 = (cw << 1) + kq;
            float sc[2][2][4];
#pragma unroll
            for (int mi = 0; mi < 2; mi++)
#pragma unroll
                for (int nbi = 0; nbi < 2; nbi++)
#pragma unroll
                    for (int q = 0; q < 4; q++) sc[mi][nbi][q] = 0.f;

#pragma unroll
            for (int kb = 0; kb < 4; kb++) {
#pragma unroll
                for (int nbi = 0; nbi < 2; nbi++) {
                    int jrow = (k4 * 2 + nbi) * 8 + g;
                    int dp = ((kb << 2) + tg) ^ g4;
                    uint2 bb = *(const uint2*)&sm.gs[buf][jrow][dp << 1];
#pragma unroll
                    for (int mi = 0; mi < 2; mi++)
                        mma_f16(sc[mi][nbi], aF[mi][kb], bb.x, bb.y);
                }
            }

            // exp + pack + STS P
#pragma unroll
            for (int mi = 0; mi < 2; mi++) {
                float e[2][4];
#pragma unroll
                for (int nbi = 0; nbi < 2; nbi++) {
                    e[nbi][0] = __expf(sc[mi][nbi][0] - SHIFT);
                    e[nbi][1] = __expf(sc[mi][nbi][1] - SHIFT);
                    e[nbi][2] = __expf(sc[mi][nbi][2] - SHIFT);
                    e[nbi][3] = __expf(sc[mi][nbi][3] - SHIFT);
                    L[mi][0] += e[nbi][0] + e[nbi][1];
                    L[mi][1] += e[nbi][2] + e[nbi][3];
                }
                int r0 = (rw << 5) + (mi << 4) + g;
                int dw = ((k4 ^ (g & 3)) << 3) + (tg << 1);
                *(uint2*)&sm.P[r0][dw] = make_uint2(
                    pk_bf16x2(e[0][0], e[0][1]), pk_bf16x2(e[1][0], e[1][1]));
                *(uint2*)&sm.P[r0 + 8][dw] = make_uint2(
                    pk_bf16x2(e[0][2], e[0][3]), pk_bf16x2(e[1][2], e[1][3]));
            }
        }
        __syncthreads();  // P complete

        // ---- PV phase: full 64 j-cols from smem P ----
#pragma unroll
        for (int k4 = 0; k4 < 4; k4++) {
            unsigned aPV[2][4];
#pragma unroll
            for (int mi = 0; mi < 2; mi++) {
                int r0 = (rw << 5) + (mi << 4) + g;
                int dw = ((k4 ^ (g & 3)) << 3) + (tg << 1);
                uint2 lo = *(const uint2*)&sm.P[r0][dw];
                uint2 hi = *(const uint2*)&sm.P[r0 + 8][dw];
                aPV[mi][0] = lo.x; aPV[mi][1] = hi.x;
                aPV[mi][2] = lo.y; aPV[mi][3] = hi.y;
            }
#pragma unroll
            for (int nb = 0; nb < 16; nb++) {
                int row = (cw << 7) + (nb << 3) + g;
                int dp = ((k4 << 2) + tg) ^ g4;
                uint2 bb = *(const uint2*)&sm.hT[buf][row][dp << 1];
#pragma unroll
                for (int mi = 0; mi < 2; mi++)
                    mma_bf16(acc[mi][nb], aPV[mi], bb.x, bb.y);
            }
        }
    }

    // ---- finalize: combine cw-partial L, divide, write o (fp16 permq) ----
#pragma unroll
    for (int mi = 0; mi < 2; mi++) {
        float l0 = L[mi][0], l1 = L[mi][1];
        l0 += __shfl_xor_sync(0xffffffffu, l0, 1);
        l0 += __shfl_xor_sync(0xffffffffu, l0, 2);
        l1 += __shfl_xor_sync(0xffffffffu, l1, 1);
        l1 += __shfl_xor_sync(0xffffffffu, l1, 2);
        if (tg == 0) {
            sm.redL[cw][(rw << 5) + (mi << 4) + g]     = l0;
            sm.redL[cw][(rw << 5) + (mi << 4) + g + 8] = l1;
        }
    }
    __syncthreads();

#pragma unroll
    for (int mi = 0; mi < 2; mi++) {
        int rl0 = (rw << 5) + (mi << 4) + g;
        float inv0 = 1.0f / (sm.redL[0][rl0] + sm.redL[1][rl0]);
        float inv1 = 1.0f / (sm.redL[0][rl0 + 8] + sm.redL[1][rl0 + 8]);
        size_t row = (size_t)b * NTOK + i0 + rl0;
#pragma unroll
        for (int nb = 0; nb < 16; nb++) {
            int col = (cw << 7) + (nb << 3) + (tg << 1);
            int pc = permq(col);
            *(__half2*)&g_o16[row * CDIM + pc] =
                __floats2half2_rn(acc[mi][nb][0] * inv0, acc[mi][nb][1] * inv0);
            *(__half2*)&g_o16[(row + 8) * CDIM + pc] =
                __floats2half2_rn(acc[mi][nb][2] * inv1, acc[mi][nb][3] * inv1);
        }
    }
#undef PREFETCH_TILE
}

// ---------------------------------------------------------------------------
extern "C" void kernel_launch(void* const* d_in, const int* in_sizes, int n_in,
                              void* d_out, int out_size) {
    const float* x     = (const float*)d_in[0];
    const float* Wf    = (const float*)d_in[1];
    const float* Wg    = (const float*)d_in[2];
    const float* Wh    = (const float*)d_in[3];
    const float* Wv    = (const float*)d_in[4];
    const float* gamma = (const float*)d_in[5];
    float* out = (float*)d_out;

    const int M = BATCH * NTOK;  // 32768

    cvt_w_k<<<(384 * 256 + 256 * 256) / 256, 256>>>(Wf, Wg, Wh, Wv);

    cudaFuncSetAttribute(proj_k, cudaFuncAttributeMaxDynamicSharedMemorySize,
                         PROJ_SMEM);
    proj_k<<<M / 64, 512, PROJ_SMEM>>>(x);

    static_assert(sizeof(AttnSmem) == 99328, "smem");
    cudaFuncSetAttribute(attn_k, cudaFuncAttributeMaxDynamicSharedMemorySize,
                         (int)sizeof(AttnSmem));
    attn_k<<<dim3(NTOK / 128, BATCH), 256, sizeof(AttnSmem)>>>();

    cudaFuncSetAttribute(epi_k, cudaFuncAttributeMaxDynamicSharedMemorySize,
                         (int)sizeof(EpiSmem));
    epi_k<<<M / 64, 512, sizeof(EpiSmem)>>>(x, gamma, out);
}